// round 9
// baseline (speedup 1.0000x reference)
#include <cuda_runtime.h>
#include <cuda_bf16.h>

// activation (N=32, C=16, H=224, W=224) fp32.
// c0-1 identity, c2-3 1x1 relu, c4-7 2x2, c8-11 4x4, c12-15 3x3.
#define HW4 12544   // float4 per image-channel
#define W4  56      // float4 per row
#define H_  224
#define Q8  1568    // HW4/8

// Per-image thread units (heavy-first), all full-density:
//   [0,     5700) : 3x3 units   (4ch * 1425, 9 f4)
//   [5700, 11972) : 4x4 units   (4ch * 1568: 8 rows x 1 f4)
//   [11972, 18244): 2x2 units   (4ch * 1568: 8 rows x 1 f4)
//   [18244, 24516): elementwise (4ch * 1568: 8 rows x 1 f4)
#define SEG_C 5700
#define SEG_B 11972
#define SEG_A 18244
#define PER_N 24516
#define TOTAL (32 * PER_N)   // 784,512

__global__ __launch_bounds__(256) void block_relu_fused(
    const float4* __restrict__ in, float4* __restrict__ out)
{
    int i = blockIdx.x * 256 + threadIdx.x;
    if (i >= TOTAL) return;
    int n = i / PER_N;
    int u = i - n * PER_N;
    const size_t nbase = (size_t)n * 16 * HW4;

    if (u >= SEG_A) {
        // ---- c0-3: identity / elementwise relu, 8 consecutive rows x 1 f4 ----
        int t  = u - SEG_A;
        int c  = t / Q8;
        int v  = t - c * Q8;
        int rq = v / W4;                   // 8-row group 0..27
        int f4 = v - rq * W4;
        size_t g = nbase + (size_t)c * HW4 + (size_t)(8 * rq) * W4 + f4;

        float4 r[8];
        #pragma unroll
        for (int j = 0; j < 8; j++) r[j] = in[g + (size_t)j * W4];
        if (c >= 2) {
            #pragma unroll
            for (int j = 0; j < 8; j++) {
                r[j].x = fmaxf(r[j].x, 0.f); r[j].y = fmaxf(r[j].y, 0.f);
                r[j].z = fmaxf(r[j].z, 0.f); r[j].w = fmaxf(r[j].w, 0.f);
            }
        }
        #pragma unroll
        for (int j = 0; j < 8; j++) out[g + (size_t)j * W4] = r[j];
    } else if (u >= SEG_C) {
        // ---- c4-11: 8 rows x 1 float4 per thread, full-density (R8 proven) ----
        bool is2x2 = (u >= SEG_B);
        int t  = u - (is2x2 ? SEG_B : SEG_C);
        int c  = (is2x2 ? 4 : 8) + t / Q8;
        int v  = t % Q8;
        int rq = v / W4;                   // 8-row group 0..27
        int f4 = v - rq * W4;
        size_t i0 = nbase + (size_t)c * HW4 + (size_t)(8 * rq) * W4 + f4;

        float4 r[8];
        #pragma unroll
        for (int j = 0; j < 8; j++) r[j] = in[i0 + (size_t)j * W4];

        if (is2x2) {
            // four vertical 2-row pairs, each with left (xy) and right (zw) masks
            #pragma unroll
            for (int p = 0; p < 4; p++) {
                float4 a = r[2 * p], b = r[2 * p + 1];
                float sx = a.x + b.x, sy = a.y + b.y, sz = a.z + b.z, sw = a.w + b.w;
                float mL = ((sx + sy) >= 0.f) ? 1.f : 0.f;
                float mR = ((sz + sw) >= 0.f) ? 1.f : 0.f;
                a.x *= mL; a.y *= mL; a.z *= mR; a.w *= mR;
                b.x *= mL; b.y *= mL; b.z *= mR; b.w *= mR;
                r[2 * p] = a; r[2 * p + 1] = b;
            }
        } else {
            // two vertical 4-row blocks, one mask each
            #pragma unroll
            for (int p = 0; p < 2; p++) {
                float cs0 = r[4*p].x + r[4*p+1].x + r[4*p+2].x + r[4*p+3].x;
                float cs1 = r[4*p].y + r[4*p+1].y + r[4*p+2].y + r[4*p+3].y;
                float cs2 = r[4*p].z + r[4*p+1].z + r[4*p+2].z + r[4*p+3].z;
                float cs3 = r[4*p].w + r[4*p+1].w + r[4*p+2].w + r[4*p+3].w;
                float m = ((cs0 + cs1 + cs2 + cs3) >= 0.f) ? 1.f : 0.f;
                #pragma unroll
                for (int j = 0; j < 4; j++) {
                    r[4*p+j].x *= m; r[4*p+j].y *= m; r[4*p+j].z *= m; r[4*p+j].w *= m;
                }
            }
        }
        #pragma unroll
        for (int j = 0; j < 8; j++) out[i0 + (size_t)j * W4] = r[j];
    } else {
        // ---- c12-15: 3x3 blocks, four blocks per thread (exact R4/R8) ----
        int c  = 12 + u / 1425;
        int v  = u % 1425;
        int br = v / 19;              // block-row 0..74
        int s  = v - br * 19;         // 12-col strip 0..18
        int r0 = br * 3;
        size_t base = nbase + (size_t)c * HW4;

        float4 val[3][3];
        #pragma unroll
        for (int r = 0; r < 3; r++) {
            int rr = r0 + r;
            bool rv = rr < H_;
            #pragma unroll
            for (int k = 0; k < 3; k++) {
                int fc = s * 3 + k;
                if (rv && fc < W4)
                    val[r][k] = in[base + (size_t)rr * W4 + fc];
                else
                    val[r][k] = make_float4(0.f, 0.f, 0.f, 0.f);
            }
        }

        float cs[12];
        #pragma unroll
        for (int k = 0; k < 3; k++) {
            cs[4 * k + 0] = val[0][k].x + val[1][k].x + val[2][k].x;
            cs[4 * k + 1] = val[0][k].y + val[1][k].y + val[2][k].y;
            cs[4 * k + 2] = val[0][k].z + val[1][k].z + val[2][k].z;
            cs[4 * k + 3] = val[0][k].w + val[1][k].w + val[2][k].w;
        }
        float m[4];
        #pragma unroll
        for (int g = 0; g < 4; g++)
            m[g] = ((cs[3 * g] + cs[3 * g + 1] + cs[3 * g + 2]) >= 0.f) ? 1.f : 0.f;

        #pragma unroll
        for (int r = 0; r < 3; r++) {
            int rr = r0 + r;
            if (rr >= H_) break;
            #pragma unroll
            for (int k = 0; k < 3; k++) {
                int fc = s * 3 + k;
                if (fc < W4) {
                    float4 tv = val[r][k];
                    int L = 4 * k;
                    tv.x *= m[(L + 0) / 3];
                    tv.y *= m[(L + 1) / 3];
                    tv.z *= m[(L + 2) / 3];
                    tv.w *= m[(L + 3) / 3];
                    out[base + (size_t)rr * W4 + fc] = tv;
                }
            }
        }
    }
}

extern "C" void kernel_launch(void* const* d_in, const int* in_sizes, int n_in,
                              void* d_out, int out_size)
{
    const float4* in  = (const float4*)d_in[0];
    float4*       out = (float4*)d_out;
    block_relu_fused<<<(TOTAL + 255) / 256, 256>>>(in, out);  // 3065 CTAs
}

// round 10
// speedup vs baseline: 1.0444x; 1.0444x over previous
#include <cuda_runtime.h>
#include <cuda_bf16.h>

// activation (N=32, C=16, H=224, W=224) fp32.
// c0-1 identity, c2-3 1x1 relu, c4-7 2x2, c8-11 4x4, c12-15 3x3.
#define HW4 12544   // float4 per image-channel
#define W4  56      // float4 per row
#define H_  224
#define Q8  1568    // HW4/8

// Per-image thread units (heavy-first), all full-density:
//   [0,     5700) : 3x3 units   (4ch * 1425, 9 f4)
//   [5700, 11972) : 4x4 units   (4ch * 1568: 8 rows x 1 f4)
//   [11972, 18244): 2x2 units   (4ch * 1568: 8 rows x 1 f4)
//   [18244, 24516): elementwise (4ch * 1568: 8 rows x 1 f4)
#define SEG_C 5700
#define SEG_B 11972
#define SEG_A 18244
#define PER_N 24516
#define TOTAL (32 * PER_N)   // 784,512

// Streaming store: evict-first in L2 so the output stream does not displace
// the (reusable across graph replays) input stream.
__device__ __forceinline__ void stcs4(float4* p, float4 v) {
    __stcs(p, v);
}

__global__ __launch_bounds__(256) void block_relu_fused(
    const float4* __restrict__ in, float4* __restrict__ out)
{
    int i = blockIdx.x * 256 + threadIdx.x;
    if (i >= TOTAL) return;
    int n = i / PER_N;
    int u = i - n * PER_N;
    const size_t nbase = (size_t)n * 16 * HW4;

    if (u >= SEG_A) {
        // ---- c0-3: identity / elementwise relu, 8 consecutive rows x 1 f4 ----
        int t  = u - SEG_A;
        int c  = t / Q8;
        int v  = t - c * Q8;
        int rq = v / W4;                   // 8-row group 0..27
        int f4 = v - rq * W4;
        size_t g = nbase + (size_t)c * HW4 + (size_t)(8 * rq) * W4 + f4;

        float4 r[8];
        #pragma unroll
        for (int j = 0; j < 8; j++) r[j] = in[g + (size_t)j * W4];
        if (c >= 2) {
            #pragma unroll
            for (int j = 0; j < 8; j++) {
                r[j].x = fmaxf(r[j].x, 0.f); r[j].y = fmaxf(r[j].y, 0.f);
                r[j].z = fmaxf(r[j].z, 0.f); r[j].w = fmaxf(r[j].w, 0.f);
            }
        }
        #pragma unroll
        for (int j = 0; j < 8; j++) stcs4(out + g + (size_t)j * W4, r[j]);
    } else if (u >= SEG_C) {
        // ---- c4-11: 8 rows x 1 float4 per thread, full-density ----
        bool is2x2 = (u >= SEG_B);
        int t  = u - (is2x2 ? SEG_B : SEG_C);
        int c  = (is2x2 ? 4 : 8) + t / Q8;
        int v  = t % Q8;
        int rq = v / W4;                   // 8-row group 0..27
        int f4 = v - rq * W4;
        size_t i0 = nbase + (size_t)c * HW4 + (size_t)(8 * rq) * W4 + f4;

        float4 r[8];
        #pragma unroll
        for (int j = 0; j < 8; j++) r[j] = in[i0 + (size_t)j * W4];

        if (is2x2) {
            // four vertical 2-row pairs, each with left (xy) and right (zw) masks
            #pragma unroll
            for (int p = 0; p < 4; p++) {
                float4 a = r[2 * p], b = r[2 * p + 1];
                float sx = a.x + b.x, sy = a.y + b.y, sz = a.z + b.z, sw = a.w + b.w;
                float mL = ((sx + sy) >= 0.f) ? 1.f : 0.f;
                float mR = ((sz + sw) >= 0.f) ? 1.f : 0.f;
                a.x *= mL; a.y *= mL; a.z *= mR; a.w *= mR;
                b.x *= mL; b.y *= mL; b.z *= mR; b.w *= mR;
                r[2 * p] = a; r[2 * p + 1] = b;
            }
        } else {
            // two vertical 4-row blocks, one mask each
            #pragma unroll
            for (int p = 0; p < 2; p++) {
                float cs0 = r[4*p].x + r[4*p+1].x + r[4*p+2].x + r[4*p+3].x;
                float cs1 = r[4*p].y + r[4*p+1].y + r[4*p+2].y + r[4*p+3].y;
                float cs2 = r[4*p].z + r[4*p+1].z + r[4*p+2].z + r[4*p+3].z;
                float cs3 = r[4*p].w + r[4*p+1].w + r[4*p+2].w + r[4*p+3].w;
                float m = ((cs0 + cs1 + cs2 + cs3) >= 0.f) ? 1.f : 0.f;
                #pragma unroll
                for (int j = 0; j < 4; j++) {
                    r[4*p+j].x *= m; r[4*p+j].y *= m; r[4*p+j].z *= m; r[4*p+j].w *= m;
                }
            }
        }
        #pragma unroll
        for (int j = 0; j < 8; j++) stcs4(out + i0 + (size_t)j * W4, r[j]);
    } else {
        // ---- c12-15: 3x3 blocks, four blocks per thread (3 rows x 12 cols) ----
        int c  = 12 + u / 1425;
        int v  = u % 1425;
        int br = v / 19;              // block-row 0..74
        int s  = v - br * 19;         // 12-col strip 0..18
        int r0 = br * 3;
        size_t base = nbase + (size_t)c * HW4;

        float4 val[3][3];
        #pragma unroll
        for (int r = 0; r < 3; r++) {
            int rr = r0 + r;
            bool rv = rr < H_;
            #pragma unroll
            for (int k = 0; k < 3; k++) {
                int fc = s * 3 + k;
                if (rv && fc < W4)
                    val[r][k] = in[base + (size_t)rr * W4 + fc];
                else
                    val[r][k] = make_float4(0.f, 0.f, 0.f, 0.f);
            }
        }

        float cs[12];
        #pragma unroll
        for (int k = 0; k < 3; k++) {
            cs[4 * k + 0] = val[0][k].x + val[1][k].x + val[2][k].x;
            cs[4 * k + 1] = val[0][k].y + val[1][k].y + val[2][k].y;
            cs[4 * k + 2] = val[0][k].z + val[1][k].z + val[2][k].z;
            cs[4 * k + 3] = val[0][k].w + val[1][k].w + val[2][k].w;
        }
        float m[4];
        #pragma unroll
        for (int g = 0; g < 4; g++)
            m[g] = ((cs[3 * g] + cs[3 * g + 1] + cs[3 * g + 2]) >= 0.f) ? 1.f : 0.f;

        #pragma unroll
        for (int r = 0; r < 3; r++) {
            int rr = r0 + r;
            if (rr >= H_) break;
            #pragma unroll
            for (int k = 0; k < 3; k++) {
                int fc = s * 3 + k;
                if (fc < W4) {
                    float4 tv = val[r][k];
                    int L = 4 * k;
                    tv.x *= m[(L + 0) / 3];
                    tv.y *= m[(L + 1) / 3];
                    tv.z *= m[(L + 2) / 3];
                    tv.w *= m[(L + 3) / 3];
                    stcs4(out + base + (size_t)rr * W4 + fc, tv);
                }
            }
        }
    }
}

extern "C" void kernel_launch(void* const* d_in, const int* in_sizes, int n_in,
                              void* d_out, int out_size)
{
    const float4* in  = (const float4*)d_in[0];
    float4*       out = (float4*)d_out;
    block_relu_fused<<<(TOTAL + 255) / 256, 256>>>(in, out);  // 3065 CTAs
}